// round 16
// baseline (speedup 1.0000x reference)
#include <cuda_runtime.h>
#include <cstdint>
#include <math.h>

#define N0V  1000000
#define N1V  40960
#define N2V  4096
#define E1V  1024000
#define E2V  40960
#define INC  100
#define HIDV 256
#define OUTV 47
#define KP   224          // padded K (14 chunks of 16)

// ---------------- scratch (static device globals; no allocation) ----------------
__device__ int   g_cnt1[N1V];
__device__ int   g_off1[N1V + 1];
__device__ int   g_cur1[N1V];
__device__ int   g_csr1[E1V];

__device__ int   g_cnt2[N2V];
__device__ int   g_off2[N2V + 1];
__device__ int   g_cur2[N2V];
__device__ int   g_csr2[E2V];

__device__ __align__(16) float g_A[(size_t)N1V * KP];      // [agg | x_dst | 0]  [N1,224]
__device__ __align__(16) float g_W1t[(size_t)HIDV * KP];   // W1 transposed+padded [256,224]
__device__ __align__(16) float g_h[(size_t)N1V * HIDV];    // layer-1 out [N1,256]
__device__ __align__(16) float g_agg2[(size_t)N2V * HIDV]; // [N2,256]

// ---------------- helpers ----------------
__device__ __forceinline__ uint32_t smem_u32(const void* p) {
    uint32_t a;
    asm("{ .reg .u64 t; cvta.to.shared.u64 t, %1; cvt.u32.u64 %0, t; }" : "=r"(a) : "l"(p));
    return a;
}

#define CP_ASYNC16(dst, src) \
    asm volatile("cp.async.cg.shared.global [%0], [%1], 16;" :: "r"(dst), "l"(src) : "memory")
#define CP_COMMIT() asm volatile("cp.async.commit_group;" ::: "memory")
#define CP_WAIT(n)  asm volatile("cp.async.wait_group %0;" :: "n"(n) : "memory")

__device__ __forceinline__ void tf32_split(float f, uint32_t& hi, uint32_t& lo) {
    uint32_t h;
    asm("cvt.rna.tf32.f32 %0, %1;" : "=r"(h) : "f"(f));
    float r = f - __uint_as_float(h);   // exact (Dekker split)
    uint32_t l;
    asm("cvt.rna.tf32.f32 %0, %1;" : "=r"(l) : "f"(r));
    hi = h; lo = l;
}

__device__ __forceinline__ void mma_tf32(float* c, const uint32_t* a, const uint32_t* b) {
    asm volatile(
        "mma.sync.aligned.m16n8k8.row.col.f32.tf32.tf32.f32 "
        "{%0,%1,%2,%3}, {%4,%5,%6,%7}, {%8,%9}, {%0,%1,%2,%3};"
        : "+f"(c[0]), "+f"(c[1]), "+f"(c[2]), "+f"(c[3])
        : "r"(a[0]), "r"(a[1]), "r"(a[2]), "r"(a[3]), "r"(b[0]), "r"(b[1]));
}

// ---------------- CSR build ----------------
__global__ void k_zero()
{
    int i = blockIdx.x * blockDim.x + threadIdx.x;
    if (i < N1V) g_cnt1[i] = 0;
    if (i < N2V) g_cnt2[i] = 0;
}

__global__ void k_count(const int* __restrict__ dst1, const int* __restrict__ dst2)
{
    int i = blockIdx.x * blockDim.x + threadIdx.x;
    if (i < E1V) atomicAdd(&g_cnt1[dst1[i]], 1);
    int j = i - E1V;
    if (j >= 0 && j < E2V) atomicAdd(&g_cnt2[dst2[j]], 1);
}

__global__ void k_scan()
{
    __shared__ int ssum[1024];
    int t = threadIdx.x;
    int *cnt, *off, *cur;
    int per, n;
    if (blockIdx.x == 0) { cnt = g_cnt1; off = g_off1; cur = g_cur1; per = N1V / 1024; n = N1V; }
    else                 { cnt = g_cnt2; off = g_off2; cur = g_cur2; per = N2V / 1024; n = N2V; }

    int base = t * per;
    int local = 0;
    for (int i = 0; i < per; i++) local += cnt[base + i];
    ssum[t] = local;
    __syncthreads();
    for (int s = 1; s < 1024; s <<= 1) {
        int v = (t >= s) ? ssum[t - s] : 0;
        __syncthreads();
        ssum[t] += v;
        __syncthreads();
    }
    int run = (t == 0) ? 0 : ssum[t - 1];
    for (int i = 0; i < per; i++) {
        int c = cnt[base + i];
        off[base + i] = run;
        cur[base + i] = run;
        run += c;
    }
    if (t == 1023) off[n] = run;
}

__global__ void k_scatter(const int* __restrict__ src1, const int* __restrict__ dst1,
                          const int* __restrict__ src2, const int* __restrict__ dst2)
{
    int i = blockIdx.x * blockDim.x + threadIdx.x;
    if (i < E1V) {
        int p = atomicAdd(&g_cur1[dst1[i]], 1);
        g_csr1[p] = src1[i];
    }
    int j = i - E1V;
    if (j >= 0 && j < E2V) {
        int p = atomicAdd(&g_cur2[dst2[j]], 1);
        g_csr2[p] = src2[j];
    }
}

// ---------------- W transpose+pad: g_W1t[n][k] ----------------
__global__ void k_wt(const float* __restrict__ W1l, const float* __restrict__ W1r)
{
    int k = blockIdx.x;        // 224
    int n = threadIdx.x;       // 256
    float v = 0.f;
    if (k < 100)      v = W1l[(size_t)k * HIDV + n];
    else if (k < 200) v = W1r[(size_t)(k - 100) * HIDV + n];
    g_W1t[(size_t)n * KP + k] = v;
}

// ---------------- layer-1 aggregation + fused A build ----------------
__global__ void k_agg1(const float* __restrict__ x)
{
    int d = blockIdx.x;
    int t = threadIdx.x;      // 128
    if (t < INC) {
        int s0 = g_off1[d], s1 = g_off1[d + 1];
        float acc = 0.f;
        int i = s0;
        for (; i + 4 <= s1; i += 4) {
            int a = g_csr1[i], b = g_csr1[i + 1], c = g_csr1[i + 2], e = g_csr1[i + 3];
            acc += x[(size_t)a * INC + t];
            acc += x[(size_t)b * INC + t];
            acc += x[(size_t)c * INC + t];
            acc += x[(size_t)e * INC + t];
        }
        for (; i < s1; i++) acc += x[(size_t)g_csr1[i] * INC + t];
        g_A[(size_t)d * KP + t] = acc / fmaxf((float)(s1 - s0), 1.f);
        g_A[(size_t)d * KP + INC + t] = x[(size_t)d * INC + t];   // x_dst copy
    } else if (t < 124) {
        g_A[(size_t)d * KP + INC + t] = 0.f;                      // pad cols 200..223
    }
}

// ---------------- layer-1 GEMM: mma.sync tf32 (3xTF32) ----------------
// h[m0:m0+128, n0:n0+128] = relu(A[m0:,224] @ W1t^T + b1l)
// BM=128 BN=128 BK=16, 8 warps (4m x 2n), warp tile 32x64 (2x8 m16n8k8).
#define BK      16
#define PADROW  20            // floats per smem row (16 + 4 pad) -> conflict-free
#define BUFSZ   (128 * PADROW)  // floats per tile (A or B)

__global__ void __launch_bounds__(256) k_gemm1_mma(const float* __restrict__ b1l)
{
    __shared__ float sm[2][2][BUFSZ];   // [buf][A/B][128*20] = 40 KB

    int tid = threadIdx.x;
    int wid = tid >> 5, lid = tid & 31;
    int lm = lid >> 2, lk = lid & 3;
    int m0 = blockIdx.y * 128;
    int n0 = blockIdx.x * 128;
    int wm = (wid & 3) * 32;            // warp m offset
    int wn = (wid >> 2) * 64;           // warp n offset

    uint32_t sbase = smem_u32(sm);

    float acc[2][8][4];
#pragma unroll
    for (int i = 0; i < 2; i++)
#pragma unroll
        for (int j = 0; j < 8; j++)
#pragma unroll
            for (int q = 0; q < 4; q++) acc[i][j][q] = 0.f;

    // async loader: chunk c -> buffer (c&1)
    auto load_chunk = [&](int c) {
        int buf = c & 1;
        uint32_t dA = sbase + (uint32_t)buf * (2 * BUFSZ * 4);
        uint32_t dB = dA + BUFSZ * 4;
#pragma unroll
        for (int i = tid; i < 512; i += 256) {
            int r = i >> 2, p = i & 3;
            const float* sa = g_A + (size_t)(m0 + r) * KP + c * BK + p * 4;
            CP_ASYNC16(dA + (uint32_t)(r * PADROW + p * 4) * 4, sa);
            const float* sb = g_W1t + (size_t)(n0 + r) * KP + c * BK + p * 4;
            CP_ASYNC16(dB + (uint32_t)(r * PADROW + p * 4) * 4, sb);
        }
        CP_COMMIT();
    };

    load_chunk(0);
    load_chunk(1);

    for (int c = 0; c < 14; c++) {
        if (c < 13) { CP_WAIT(1); } else { CP_WAIT(0); }
        __syncthreads();

        const float* As = sm[c & 1][0];
        const float* Bs = sm[c & 1][1];

#pragma unroll
        for (int ks = 0; ks < 2; ks++) {
            int kb = ks * 8;
            uint32_t ah[2][4], al[2][4];
#pragma unroll
            for (int mi = 0; mi < 2; mi++) {
                int r = wm + mi * 16 + lm;
                tf32_split(As[r * PADROW + kb + lk],            ah[mi][0], al[mi][0]);
                tf32_split(As[(r + 8) * PADROW + kb + lk],      ah[mi][1], al[mi][1]);
                tf32_split(As[r * PADROW + kb + 4 + lk],        ah[mi][2], al[mi][2]);
                tf32_split(As[(r + 8) * PADROW + kb + 4 + lk],  ah[mi][3], al[mi][3]);
            }
#pragma unroll
            for (int half = 0; half < 2; half++) {
                uint32_t bh[4][2], bl[4][2];
#pragma unroll
                for (int nj = 0; nj < 4; nj++) {
                    int nn = wn + (half * 4 + nj) * 8 + lm;
                    tf32_split(Bs[nn * PADROW + kb + lk],     bh[nj][0], bl[nj][0]);
                    tf32_split(Bs[nn * PADROW + kb + 4 + lk], bh[nj][1], bl[nj][1]);
                }
#pragma unroll
                for (int mi = 0; mi < 2; mi++)
#pragma unroll
                    for (int nj = 0; nj < 4; nj++) {
                        float* cc = acc[mi][half * 4 + nj];
                        mma_tf32(cc, al[mi], bh[nj]);   // low-order terms first
                        mma_tf32(cc, ah[mi], bl[nj]);
                        mma_tf32(cc, ah[mi], bh[nj]);
                    }
            }
        }

        if (c < 12) {
            __syncthreads();      // everyone done reading buffer (c&1)
            load_chunk(c + 2);
        }
    }

    // epilogue: bias + relu, float2 stores
#pragma unroll
    for (int ni = 0; ni < 8; ni++) {
        int n = n0 + wn + ni * 8 + lk * 2;
        float bz0 = __ldg(&b1l[n]), bz1 = __ldg(&b1l[n + 1]);
#pragma unroll
        for (int mi = 0; mi < 2; mi++) {
            int r0 = m0 + wm + mi * 16 + lm;
            float2 o0, o1;
            o0.x = fmaxf(acc[mi][ni][0] + bz0, 0.f);
            o0.y = fmaxf(acc[mi][ni][1] + bz1, 0.f);
            o1.x = fmaxf(acc[mi][ni][2] + bz0, 0.f);
            o1.y = fmaxf(acc[mi][ni][3] + bz1, 0.f);
            *(float2*)(g_h + (size_t)r0 * HIDV + n) = o0;
            *(float2*)(g_h + (size_t)(r0 + 8) * HIDV + n) = o1;
        }
    }
}

// ---------------- layer-2 aggregation ----------------
__global__ void k_agg2()
{
    int d = blockIdx.x;
    int t = threadIdx.x;   // 256
    int s0 = g_off2[d], s1 = g_off2[d + 1];

    float acc = 0.f;
    int i = s0;
    for (; i + 4 <= s1; i += 4) {
        int a = g_csr2[i], b = g_csr2[i + 1], c = g_csr2[i + 2], e = g_csr2[i + 3];
        acc += g_h[(size_t)a * HIDV + t];
        acc += g_h[(size_t)b * HIDV + t];
        acc += g_h[(size_t)c * HIDV + t];
        acc += g_h[(size_t)e * HIDV + t];
    }
    for (; i < s1; i++) acc += g_h[(size_t)g_csr2[i] * HIDV + t];

    g_agg2[(size_t)d * HIDV + t] = acc / fmaxf((float)(s1 - s0), 1.f);
}

// ---------------- layer 2 + log_softmax ----------------
__global__ void k_layer2(const float* __restrict__ W2l,
                         const float* __restrict__ b2l,
                         const float* __restrict__ W2r,
                         float* __restrict__ out)
{
    int m = blockIdx.x;
    int t = threadIdx.x;   // 64
    __shared__ float sa[HIDV], sh[HIDV];
    __shared__ float red[64];

    for (int i = t; i < HIDV; i += 64) {
        sa[i] = g_agg2[(size_t)m * HIDV + i];
        sh[i] = g_h[(size_t)m * HIDV + i];
    }
    __syncthreads();

    float v = -1e30f;
    if (t < OUTV) {
        float acc = b2l[t];
#pragma unroll 8
        for (int k = 0; k < HIDV; k++)
            acc += sa[k] * W2l[k * OUTV + t] + sh[k] * W2r[k * OUTV + t];
        v = acc;
    }

    red[t] = v;
    __syncthreads();
#pragma unroll
    for (int s = 32; s > 0; s >>= 1) {
        if (t < s) red[t] = fmaxf(red[t], red[t + s]);
        __syncthreads();
    }
    float mx = red[0];
    __syncthreads();

    float ev = (t < OUTV) ? expf(v - mx) : 0.f;
    red[t] = ev;
    __syncthreads();
#pragma unroll
    for (int s = 32; s > 0; s >>= 1) {
        if (t < s) red[t] += red[t + s];
        __syncthreads();
    }
    float lse = logf(red[0]);

    if (t < OUTV) out[(size_t)m * OUTV + t] = v - mx - lse;
}

// ---------------- launch ----------------
extern "C" void kernel_launch(void* const* d_in, const int* in_sizes, int n_in,
                              void* d_out, int out_size)
{
    const float* x    = (const float*)d_in[0];
    const float* W1l  = (const float*)d_in[1];
    const float* b1l  = (const float*)d_in[2];
    const float* W1r  = (const float*)d_in[3];
    const float* W2l  = (const float*)d_in[4];
    const float* b2l  = (const float*)d_in[5];
    const float* W2r  = (const float*)d_in[6];
    const int*   src1 = (const int*)d_in[7];
    const int*   dst1 = (const int*)d_in[8];
    const int*   src2 = (const int*)d_in[9];
    const int*   dst2 = (const int*)d_in[10];
    float* out = (float*)d_out;

    int tot = E1V + E2V;

    k_wt<<<KP, HIDV>>>(W1l, W1r);
    k_zero<<<(N1V + 255) / 256, 256>>>();
    k_count<<<(tot + 255) / 256, 256>>>(dst1, dst2);
    k_scan<<<2, 1024>>>();
    k_scatter<<<(tot + 255) / 256, 256>>>(src1, dst1, src2, dst2);
    k_agg1<<<N1V, 128>>>(x);
    dim3 g1(2, 320);
    k_gemm1_mma<<<g1, 256>>>(b1l);
    k_agg2<<<N2V, 256>>>();
    k_layer2<<<N2V, 64>>>(W2l, b2l, W2r, out);
}

// round 17
// speedup vs baseline: 1.0007x; 1.0007x over previous
#include <cuda_runtime.h>
#include <cstdint>
#include <math.h>

#define N0V  1000000
#define N1V  40960
#define N2V  4096
#define E1V  1024000
#define E2V  40960
#define INC  100
#define HIDV 256
#define OUTV 47
#define KP   224          // padded K (14 chunks of 16)

// ---------------- scratch (static device globals; no allocation) ----------------
__device__ int   g_cnt1[N1V];
__device__ int   g_off1[N1V + 1];
__device__ int   g_cur1[N1V];
__device__ int   g_csr1[E1V];

__device__ int   g_cnt2[N2V];
__device__ int   g_off2[N2V + 1];
__device__ int   g_cur2[N2V];
__device__ int   g_csr2[E2V];

__device__ __align__(16) float g_A[(size_t)N1V * KP];      // [agg | x_dst | 0]  [N1,224]
__device__ __align__(16) float g_W1t[(size_t)HIDV * KP];   // W1 transposed+padded [256,224]
__device__ __align__(16) float g_h[(size_t)N1V * HIDV];    // layer-1 out [N1,256]
__device__ __align__(16) float g_agg2[(size_t)N2V * HIDV]; // [N2,256]

// ---------------- helpers ----------------
__device__ __forceinline__ uint32_t smem_u32(const void* p) {
    uint32_t a;
    asm("{ .reg .u64 t; cvta.to.shared.u64 t, %1; cvt.u32.u64 %0, t; }" : "=r"(a) : "l"(p));
    return a;
}

#define CP_ASYNC16(dst, src) \
    asm volatile("cp.async.cg.shared.global [%0], [%1], 16;" :: "r"(dst), "l"(src) : "memory")
#define CP_COMMIT() asm volatile("cp.async.commit_group;" ::: "memory")
#define CP_WAIT(n)  asm volatile("cp.async.wait_group %0;" :: "n"(n) : "memory")

__device__ __forceinline__ void tf32_split(float f, uint32_t& hi, uint32_t& lo) {
    uint32_t h;
    asm("cvt.rna.tf32.f32 %0, %1;" : "=r"(h) : "f"(f));
    float r = f - __uint_as_float(h);   // exact (Dekker split)
    uint32_t l;
    asm("cvt.rna.tf32.f32 %0, %1;" : "=r"(l) : "f"(r));
    hi = h; lo = l;
}

__device__ __forceinline__ void mma_tf32(float* c, const uint32_t* a, const uint32_t* b) {
    asm volatile(
        "mma.sync.aligned.m16n8k8.row.col.f32.tf32.tf32.f32 "
        "{%0,%1,%2,%3}, {%4,%5,%6,%7}, {%8,%9}, {%0,%1,%2,%3};"
        : "+f"(c[0]), "+f"(c[1]), "+f"(c[2]), "+f"(c[3])
        : "r"(a[0]), "r"(a[1]), "r"(a[2]), "r"(a[3]), "r"(b[0]), "r"(b[1]));
}

// ---------------- CSR build ----------------
__global__ void k_zero()
{
    int i = blockIdx.x * blockDim.x + threadIdx.x;
    if (i < N1V) g_cnt1[i] = 0;
    if (i < N2V) g_cnt2[i] = 0;
}

__global__ void k_count(const int* __restrict__ dst1, const int* __restrict__ dst2)
{
    int i = blockIdx.x * blockDim.x + threadIdx.x;
    if (i < E1V) atomicAdd(&g_cnt1[dst1[i]], 1);
    int j = i - E1V;
    if (j >= 0 && j < E2V) atomicAdd(&g_cnt2[dst2[j]], 1);
}

__global__ void k_scan()
{
    __shared__ int ssum[1024];
    int t = threadIdx.x;
    int *cnt, *off, *cur;
    int per, n;
    if (blockIdx.x == 0) { cnt = g_cnt1; off = g_off1; cur = g_cur1; per = N1V / 1024; n = N1V; }
    else                 { cnt = g_cnt2; off = g_off2; cur = g_cur2; per = N2V / 1024; n = N2V; }

    int base = t * per;
    int local = 0;
    for (int i = 0; i < per; i++) local += cnt[base + i];
    ssum[t] = local;
    __syncthreads();
    for (int s = 1; s < 1024; s <<= 1) {
        int v = (t >= s) ? ssum[t - s] : 0;
        __syncthreads();
        ssum[t] += v;
        __syncthreads();
    }
    int run = (t == 0) ? 0 : ssum[t - 1];
    for (int i = 0; i < per; i++) {
        int c = cnt[base + i];
        off[base + i] = run;
        cur[base + i] = run;
        run += c;
    }
    if (t == 1023) off[n] = run;
}

__global__ void k_scatter(const int* __restrict__ src1, const int* __restrict__ dst1,
                          const int* __restrict__ src2, const int* __restrict__ dst2)
{
    int i = blockIdx.x * blockDim.x + threadIdx.x;
    if (i < E1V) {
        int p = atomicAdd(&g_cur1[dst1[i]], 1);
        g_csr1[p] = src1[i];
    }
    int j = i - E1V;
    if (j >= 0 && j < E2V) {
        int p = atomicAdd(&g_cur2[dst2[j]], 1);
        g_csr2[p] = src2[j];
    }
}

// ---------------- W transpose+pad: g_W1t[n][k] ----------------
__global__ void k_wt(const float* __restrict__ W1l, const float* __restrict__ W1r)
{
    int k = blockIdx.x;        // 224
    int n = threadIdx.x;       // 256
    float v = 0.f;
    if (k < 100)      v = W1l[(size_t)k * HIDV + n];
    else if (k < 200) v = W1r[(size_t)(k - 100) * HIDV + n];
    g_W1t[(size_t)n * KP + k] = v;
}

// ---------------- layer-1 aggregation + fused A build ----------------
__global__ void k_agg1(const float* __restrict__ x)
{
    int d = blockIdx.x;
    int t = threadIdx.x;      // 128
    if (t < INC) {
        int s0 = g_off1[d], s1 = g_off1[d + 1];
        float acc = 0.f;
        int i = s0;
        for (; i + 4 <= s1; i += 4) {
            int a = g_csr1[i], b = g_csr1[i + 1], c = g_csr1[i + 2], e = g_csr1[i + 3];
            acc += x[(size_t)a * INC + t];
            acc += x[(size_t)b * INC + t];
            acc += x[(size_t)c * INC + t];
            acc += x[(size_t)e * INC + t];
        }
        for (; i < s1; i++) acc += x[(size_t)g_csr1[i] * INC + t];
        g_A[(size_t)d * KP + t] = acc / fmaxf((float)(s1 - s0), 1.f);
        g_A[(size_t)d * KP + INC + t] = x[(size_t)d * INC + t];   // x_dst copy
    } else if (t < 124) {
        g_A[(size_t)d * KP + INC + t] = 0.f;                      // pad cols 200..223
    }
}

// ---------------- layer-1 GEMM: mma.sync tf32 (3xTF32) ----------------
// h[m0:m0+128, n0:n0+128] = relu(A[m0:,224] @ W1t^T + b1l)
// BM=128 BN=128 BK=16, 8 warps (4m x 2n), warp tile 32x64 (2x8 m16n8k8).
#define BK      16
#define PADROW  20            // floats per smem row (16 + 4 pad) -> conflict-free
#define BUFSZ   (128 * PADROW)  // floats per tile (A or B)

__global__ void __launch_bounds__(256) k_gemm1_mma(const float* __restrict__ b1l)
{
    __shared__ float sm[2][2][BUFSZ];   // [buf][A/B][128*20] = 40 KB

    int tid = threadIdx.x;
    int wid = tid >> 5, lid = tid & 31;
    int lm = lid >> 2, lk = lid & 3;
    int m0 = blockIdx.y * 128;
    int n0 = blockIdx.x * 128;
    int wm = (wid & 3) * 32;            // warp m offset
    int wn = (wid >> 2) * 64;           // warp n offset

    uint32_t sbase = smem_u32(sm);

    float acc[2][8][4];
#pragma unroll
    for (int i = 0; i < 2; i++)
#pragma unroll
        for (int j = 0; j < 8; j++)
#pragma unroll
            for (int q = 0; q < 4; q++) acc[i][j][q] = 0.f;

    // async loader: chunk c -> buffer (c&1)
    auto load_chunk = [&](int c) {
        int buf = c & 1;
        uint32_t dA = sbase + (uint32_t)buf * (2 * BUFSZ * 4);
        uint32_t dB = dA + BUFSZ * 4;
#pragma unroll
        for (int i = tid; i < 512; i += 256) {
            int r = i >> 2, p = i & 3;
            const float* sa = g_A + (size_t)(m0 + r) * KP + c * BK + p * 4;
            CP_ASYNC16(dA + (uint32_t)(r * PADROW + p * 4) * 4, sa);
            const float* sb = g_W1t + (size_t)(n0 + r) * KP + c * BK + p * 4;
            CP_ASYNC16(dB + (uint32_t)(r * PADROW + p * 4) * 4, sb);
        }
        CP_COMMIT();
    };

    load_chunk(0);
    load_chunk(1);

    for (int c = 0; c < 14; c++) {
        if (c < 13) { CP_WAIT(1); } else { CP_WAIT(0); }
        __syncthreads();

        const float* As = sm[c & 1][0];
        const float* Bs = sm[c & 1][1];

#pragma unroll
        for (int ks = 0; ks < 2; ks++) {
            int kb = ks * 8;
            uint32_t ah[2][4], al[2][4];
#pragma unroll
            for (int mi = 0; mi < 2; mi++) {
                int r = wm + mi * 16 + lm;
                tf32_split(As[r * PADROW + kb + lk],            ah[mi][0], al[mi][0]);
                tf32_split(As[(r + 8) * PADROW + kb + lk],      ah[mi][1], al[mi][1]);
                tf32_split(As[r * PADROW + kb + 4 + lk],        ah[mi][2], al[mi][2]);
                tf32_split(As[(r + 8) * PADROW + kb + 4 + lk],  ah[mi][3], al[mi][3]);
            }
#pragma unroll
            for (int half = 0; half < 2; half++) {
                uint32_t bh[4][2], bl[4][2];
#pragma unroll
                for (int nj = 0; nj < 4; nj++) {
                    int nn = wn + (half * 4 + nj) * 8 + lm;
                    tf32_split(Bs[nn * PADROW + kb + lk],     bh[nj][0], bl[nj][0]);
                    tf32_split(Bs[nn * PADROW + kb + 4 + lk], bh[nj][1], bl[nj][1]);
                }
#pragma unroll
                for (int mi = 0; mi < 2; mi++)
#pragma unroll
                    for (int nj = 0; nj < 4; nj++) {
                        float* cc = acc[mi][half * 4 + nj];
                        mma_tf32(cc, al[mi], bh[nj]);   // low-order terms first
                        mma_tf32(cc, ah[mi], bl[nj]);
                        mma_tf32(cc, ah[mi], bh[nj]);
                    }
            }
        }

        if (c < 12) {
            __syncthreads();      // everyone done reading buffer (c&1)
            load_chunk(c + 2);
        }
    }

    // epilogue: bias + relu, float2 stores
#pragma unroll
    for (int ni = 0; ni < 8; ni++) {
        int n = n0 + wn + ni * 8 + lk * 2;
        float bz0 = __ldg(&b1l[n]), bz1 = __ldg(&b1l[n + 1]);
#pragma unroll
        for (int mi = 0; mi < 2; mi++) {
            int r0 = m0 + wm + mi * 16 + lm;
            float2 o0, o1;
            o0.x = fmaxf(acc[mi][ni][0] + bz0, 0.f);
            o0.y = fmaxf(acc[mi][ni][1] + bz1, 0.f);
            o1.x = fmaxf(acc[mi][ni][2] + bz0, 0.f);
            o1.y = fmaxf(acc[mi][ni][3] + bz1, 0.f);
            *(float2*)(g_h + (size_t)r0 * HIDV + n) = o0;
            *(float2*)(g_h + (size_t)(r0 + 8) * HIDV + n) = o1;
        }
    }
}

// ---------------- layer-2 aggregation ----------------
__global__ void k_agg2()
{
    int d = blockIdx.x;
    int t = threadIdx.x;   // 256
    int s0 = g_off2[d], s1 = g_off2[d + 1];

    float acc = 0.f;
    int i = s0;
    for (; i + 4 <= s1; i += 4) {
        int a = g_csr2[i], b = g_csr2[i + 1], c = g_csr2[i + 2], e = g_csr2[i + 3];
        acc += g_h[(size_t)a * HIDV + t];
        acc += g_h[(size_t)b * HIDV + t];
        acc += g_h[(size_t)c * HIDV + t];
        acc += g_h[(size_t)e * HIDV + t];
    }
    for (; i < s1; i++) acc += g_h[(size_t)g_csr2[i] * HIDV + t];

    g_agg2[(size_t)d * HIDV + t] = acc / fmaxf((float)(s1 - s0), 1.f);
}

// ---------------- layer 2 + log_softmax ----------------
__global__ void k_layer2(const float* __restrict__ W2l,
                         const float* __restrict__ b2l,
                         const float* __restrict__ W2r,
                         float* __restrict__ out)
{
    int m = blockIdx.x;
    int t = threadIdx.x;   // 64
    __shared__ float sa[HIDV], sh[HIDV];
    __shared__ float red[64];

    for (int i = t; i < HIDV; i += 64) {
        sa[i] = g_agg2[(size_t)m * HIDV + i];
        sh[i] = g_h[(size_t)m * HIDV + i];
    }
    __syncthreads();

    float v = -1e30f;
    if (t < OUTV) {
        float acc = b2l[t];
#pragma unroll 8
        for (int k = 0; k < HIDV; k++)
            acc += sa[k] * W2l[k * OUTV + t] + sh[k] * W2r[k * OUTV + t];
        v = acc;
    }

    red[t] = v;
    __syncthreads();
#pragma unroll
    for (int s = 32; s > 0; s >>= 1) {
        if (t < s) red[t] = fmaxf(red[t], red[t + s]);
        __syncthreads();
    }
    float mx = red[0];
    __syncthreads();

    float ev = (t < OUTV) ? expf(v - mx) : 0.f;
    red[t] = ev;
    __syncthreads();
#pragma unroll
    for (int s = 32; s > 0; s >>= 1) {
        if (t < s) red[t] += red[t + s];
        __syncthreads();
    }
    float lse = logf(red[0]);

    if (t < OUTV) out[(size_t)m * OUTV + t] = v - mx - lse;
}

// ---------------- launch ----------------
extern "C" void kernel_launch(void* const* d_in, const int* in_sizes, int n_in,
                              void* d_out, int out_size)
{
    const float* x    = (const float*)d_in[0];
    const float* W1l  = (const float*)d_in[1];
    const float* b1l  = (const float*)d_in[2];
    const float* W1r  = (const float*)d_in[3];
    const float* W2l  = (const float*)d_in[4];
    const float* b2l  = (const float*)d_in[5];
    const float* W2r  = (const float*)d_in[6];
    const int*   src1 = (const int*)d_in[7];
    const int*   dst1 = (const int*)d_in[8];
    const int*   src2 = (const int*)d_in[9];
    const int*   dst2 = (const int*)d_in[10];
    float* out = (float*)d_out;

    int tot = E1V + E2V;

    k_wt<<<KP, HIDV>>>(W1l, W1r);
    k_zero<<<(N1V + 255) / 256, 256>>>();
    k_count<<<(tot + 255) / 256, 256>>>(dst1, dst2);
    k_scan<<<2, 1024>>>();
    k_scatter<<<(tot + 255) / 256, 256>>>(src1, dst1, src2, dst2);
    k_agg1<<<N1V, 128>>>(x);
    dim3 g1(2, 320);
    k_gemm1_mma<<<g1, 256>>>(b1l);
    k_agg2<<<N2V, 256>>>();
    k_layer2<<<N2V, 64>>>(W2l, b2l, W2r, out);
}